// round 5
// baseline (speedup 1.0000x reference)
#include <cuda_runtime.h>
#include <math.h>

// ---------------------------------------------------------------------------
// InvariantPolynomial: out = SILU_CST * sum_e x_left[oi[e]] * x_right[e] * f(|pos_e|)
// f(d) = sum_j silu( (emb(d) @ W1/sqrt(20))_j ) * (rowsum(W2)/sqrt(30))_j
// sh[:, :1] == 1 identically (l=0 SH) -> SH block is dead code.
// R4 lesson: 3-launch pipeline = 2 near-empty latency bubbles (~7us).
// Now: ONE persistent kernel. Co-resident grid, software grid barrier
// (replay-safe monotone counter), last-ticket block does the final reduce.
// ---------------------------------------------------------------------------

#define TABLE_N 8192
#define D_MAX   5.25f               // all 20 gaussian emb underflow in fp32 for d >= ~4.8
#define QN      8192                // quadrature intervals (8193 points)
#define QH      (24.0f / 8192.0f)   // exactly representable step
#define NTB     32                  // table blocks   (32*256 = 8192 entries)
#define NQBK    32                  // quad blocks    (32*256 = 8192 pts + endpoint)
#define NSETUP  (NTB + NQBK)
#define MAXG    4096

__device__ float    g_tab[TABLE_N];
__device__ float    g_qpart[NQBK + 1];
__device__ double   g_mpart[MAXG];
__device__ unsigned g_arrive;       // monotone across replays
__device__ unsigned g_done;         // monotone across replays

__device__ __forceinline__ float silu_f(float p) {
    return __fdividef(p, 1.0f + __expf(-p));
}

__device__ __forceinline__ float edge_term(float x, float y, float z,
                                           float w, int id,
                                           const float* __restrict__ xleft) {
    float d  = sqrtf(fmaf(x, x, fmaf(y, y, z * z)));
    float ft = fminf(d * ((float)(TABLE_N - 1) / D_MAX), (float)(TABLE_N - 1));
    int   i  = min((int)ft, TABLE_N - 2);
    float f0 = g_tab[i];
    float f1 = g_tab[i + 1];
    float f  = fmaf(ft - (float)i, f1 - f0, f0);        // == 0 near/above D_MAX
    return f * w * __ldg(&xleft[id]);
}

__global__ void __launch_bounds__(256, 4)
fused_kernel(const float4* __restrict__ pos4,
             const float4* __restrict__ xr4,
             const int4*   __restrict__ idx4,
             const float*  __restrict__ xleft,
             const float*  __restrict__ pos,
             const float*  __restrict__ xr,
             const int*    __restrict__ idx,
             const float*  __restrict__ W1,
             const float*  __restrict__ W2,
             float* __restrict__ out,
             int nq, int E, int G) {
    const int bid = blockIdx.x, tid = threadIdx.x;
    __shared__ float sred[256];

    // ===================== phase 1: setup slices =====================
    if (bid < NTB) {
        // ---- f(d) table, one entry per thread ----
        __shared__ float sW1[600];   // W1 [20,30] row-major
        __shared__ float sW2s[30];   // rowsum(W2)/sqrt(30)
        for (int i = tid; i < 600; i += 256) sW1[i] = W1[i];
        if (tid < 30) {
            float s = 0.f;
            #pragma unroll
            for (int c = 0; c < 5; c++) s += W2[tid * 5 + c];
            sW2s[tid] = s * 0.18257418583505536f;       // 1/sqrt(30)
        }
        __syncthreads();

        int   i = bid * 256 + tid;                      // 0..8191
        float d = (float)i * (D_MAX / (float)(TABLE_N - 1));

        float e[20];
        #pragma unroll
        for (int k = 0; k < 20; k++) {
            float vk   = (float)(k + 1) * (3.5f / 21.0f);
            float diff = (d - vk) * (21.0f / 3.5f);
            e[k] = __expf(-diff * diff) * (1.0f / 1.12f);
        }
        float pre[30];
        #pragma unroll
        for (int j = 0; j < 30; j++) pre[j] = 0.f;
        #pragma unroll
        for (int k = 0; k < 20; k++) {
            #pragma unroll
            for (int j = 0; j < 30; j++) pre[j] = fmaf(e[k], sW1[k * 30 + j], pre[j]);
        }
        float f = 0.f;
        #pragma unroll
        for (int j = 0; j < 30; j++) {
            float p = pre[j] * 0.22360679774997896f;    // 1/sqrt(20)
            f = fmaf(silu_f(p), sW2s[j], f);
        }
        g_tab[i] = f;
    } else if (bid < NSETUP) {
        // ---- trapezoid quadrature for silu normalize2mom ----
        int   i = (bid - NTB) * 256 + tid;              // 0..8191
        float z   = fmaf((float)i, QH, -12.0f);
        float s   = silu_f(z);
        float phi = 0.3989422804014327f * __expf(-0.5f * z * z);
        float v   = s * s * phi;
        if (i == 0) v *= 0.5f;                          // left end weight
        sred[tid] = v;
        __syncthreads();
        #pragma unroll
        for (int st = 128; st > 0; st >>= 1) {
            if (tid < st) sred[tid] += sred[tid + st];
            __syncthreads();
        }
        if (tid == 0) g_qpart[bid - NTB] = sred[0];
        if (bid == NTB && tid == 1) {
            // right endpoint z = +12, weight 0.5
            float s2   = silu_f(12.0f);
            float phi2 = 0.3989422804014327f * __expf(-0.5f * 144.0f);
            g_qpart[NQBK] = 0.5f * s2 * s2 * phi2;
        }
    }

    // ===================== grid barrier (replay-safe) =====================
    __threadfence();                                    // publish setup writes
    __shared__ unsigned goal_s;
    if (tid == 0) {
        unsigned old = atomicAdd(&g_arrive, 1u);
        goal_s = (old / (unsigned)G + 1u) * (unsigned)G;
    }
    __syncthreads();
    if (tid == 0) {
        unsigned goal = goal_s;
        while (*((volatile unsigned*)&g_arrive) < goal) __nanosleep(64);
    }
    __syncthreads();
    __threadfence();                                    // acquire before table reads

    // ===================== phase 2: main pass =====================
    float local = 0.f;
    for (int t = bid * 256 + tid; t < nq; t += G * 256) {
        float4 a = pos4[3 * t];
        float4 b = pos4[3 * t + 1];
        float4 c = pos4[3 * t + 2];
        float4 w = xr4[t];
        int4  id = idx4[t];
        local += edge_term(a.x, a.y, a.z, w.x, id.x, xleft);
        local += edge_term(a.w, b.x, b.y, w.y, id.y, xleft);
        local += edge_term(b.z, b.w, c.x, w.z, id.z, xleft);
        local += edge_term(c.y, c.z, c.w, w.w, id.w, xleft);
    }
    if (bid == 0 && tid == 0) {                         // tail edges (E % 4)
        for (int e2 = nq * 4; e2 < E; e2++)
            local += edge_term(pos[3 * e2], pos[3 * e2 + 1], pos[3 * e2 + 2],
                               xr[e2], idx[e2], xleft);
    }

    // block reduction -> per-block double partial
    #pragma unroll
    for (int o = 16; o > 0; o >>= 1)
        local += __shfl_down_sync(0xffffffffu, local, o);
    __shared__ float warpsum[8];
    int lane = tid & 31, wid = tid >> 5;
    if (lane == 0) warpsum[wid] = local;
    __syncthreads();
    if (wid == 0) {
        float v = (lane < 8) ? warpsum[lane] : 0.f;
        #pragma unroll
        for (int o = 4; o > 0; o >>= 1)
            v += __shfl_down_sync(0xffffffffu, v, o);
        if (lane == 0) g_mpart[bid] = (double)v;
    }

    // ===================== phase 3: last block finalizes =====================
    __threadfence();                                    // publish partial
    __shared__ unsigned last_s;
    if (tid == 0) {
        unsigned t = atomicAdd(&g_done, 1u);
        last_s = ((t % (unsigned)G) == (unsigned)(G - 1)) ? 1u : 0u;
    }
    __syncthreads();
    if (!last_s) return;

    __threadfence();                                    // acquire all partials
    __shared__ double redm[256], redq[256];
    double m = 0.0, q = 0.0;
    for (int i = tid; i < G; i += 256) m += ((volatile double*)g_mpart)[i];
    for (int i = tid; i <= NQBK; i += 256) q += (double)((volatile float*)g_qpart)[i];
    redm[tid] = m;
    redq[tid] = q;
    __syncthreads();
    #pragma unroll
    for (int s = 128; s > 0; s >>= 1) {
        if (tid < s) { redm[tid] += redm[tid + s]; redq[tid] += redq[tid + s]; }
        __syncthreads();
    }
    if (tid == 0) {
        double integral = (double)QH * redq[0];
        double cst = 1.0 / sqrt(integral);              // ~1.679 silu normalize2mom
        out[0] = (float)(redm[0] * cst);
    }
}

// ---------------------------------------------------------------------------
extern "C" void kernel_launch(void* const* d_in, const int* in_sizes, int n_in,
                              void* d_out, int out_size) {
    const float* pos = (const float*)d_in[0];   // [E,3]
    const float* xr  = (const float*)d_in[1];   // [E,1]
    const float* xl  = (const float*)d_in[2];   // [N,1]
    const float* W1  = (const float*)d_in[3];   // [20,30]
    const float* W2  = (const float*)d_in[4];   // [30,5]
    const int*   oi  = (const int*)d_in[5];     // [E]

    int E = in_sizes[1];
    if (E < 0) E = 0;
    int nq = E / 4;

    // co-resident grid size: SMs * max-active-blocks (host queries, capture-safe)
    int dev = 0;  cudaGetDevice(&dev);
    int nsm = 0;  cudaDeviceGetAttribute(&nsm, cudaDevAttrMultiProcessorCount, dev);
    int bpm = 0;
    cudaOccupancyMaxActiveBlocksPerMultiprocessor(&bpm, fused_kernel, 256, 0);
    if (nsm <= 0) nsm = 64;
    if (bpm <= 0) bpm = 1;
    long long g = (long long)nsm * bpm;
    int G = (g > MAXG) ? MAXG : (int)g;
    if (G < NSETUP) G = NSETUP;                 // all setup blocks must exist

    fused_kernel<<<G, 256>>>((const float4*)pos, (const float4*)xr,
                             (const int4*)oi, xl, pos, xr, oi,
                             W1, W2, (float*)d_out, nq, E, G);
}